// round 1
// baseline (speedup 1.0000x reference)
#include <cuda_runtime.h>
#include <math.h>

// Problem constants
#define KK 64
#define DD 64
#define BB 16
#define NTOK 16384
#define SPLIT 32                 // CTAs per batch
#define TT 64                    // tokens per chunk
#define TOK_PER_CTA (NTOK / SPLIT)   // 512
#define NCHUNKS (TOK_PER_CTA / TT)   // 8
#define NTHREADS 256
#define PSIZE (KK + 2 * KK * DD)     // 8256 partial floats per CTA

#define FSTRIDE 130              // f_sh row stride (floats), even for 8B-aligned f32x2
#define LSTRIDE 66               // logits/Q row stride
#define LOG2E 1.4426950408889634f

// smem layout (floats): W[8192] | f[64*130=8320] | L[64*66=4224] | c[64]
#define SM_W 0
#define SM_F 8192
#define SM_L (8192 + 8320)
#define SM_C (SM_L + 4224)
#define SMEM_FLOATS (SM_C + 64)
#define SMEM_BYTES (SMEM_FLOATS * 4)   // 83200

__device__ float g_W[KK * 128];
__device__ float g_c[KK];
__device__ float g_scratch[BB * SPLIT * PSIZE];   // 512 * 8256 floats

// ---------------- packed f32x2 helpers (sm_100+) ----------------
__device__ __forceinline__ void fma2(unsigned long long &d,
                                     unsigned long long a,
                                     unsigned long long b) {
    asm("fma.rn.f32x2 %0, %1, %2, %0;" : "+l"(d) : "l"(a), "l"(b));
}
__device__ __forceinline__ unsigned long long pack2(float x) {
    unsigned long long r;
    asm("mov.b64 %0, {%1, %1};" : "=l"(r) : "f"(x));
    return r;
}
__device__ __forceinline__ float2 unpk(unsigned long long v) {
    float2 r;
    asm("mov.b64 {%0, %1}, %2;" : "=f"(r.x), "=f"(r.y) : "l"(v));
    return r;
}
__device__ __forceinline__ float ex2f(float x) {
    float r;
    asm("ex2.approx.f32 %0, %1;" : "=f"(r) : "f"(x));
    return r;
}

// ---------------- prep: fold weights/constants -------------------
// logit*log2e = sum_j W[k,j]*f[j] + c[k],  f=[x^2 (0..63), x (64..127)]
// W[k,d]    = -0.5/var * log2e
// W[k,64+d] =  mu/var  * log2e
// c[k]      = (-0.5*(D*ln(2pi) + sum log var + sum mu^2/var) + ln pi) * log2e
__global__ void fv_prep_kernel(const float* __restrict__ pi,
                               const float* __restrict__ mu,
                               const float* __restrict__ var) {
    int k = threadIdx.x;
    if (k >= KK) return;
    float logdet = 0.f, quad = 0.f;
    for (int d = 0; d < DD; d++) {
        float v = var[k * DD + d];
        float m = mu[k * DD + d];
        float iv = 1.0f / v;
        g_W[k * 128 + d]      = -0.5f * iv * LOG2E;
        g_W[k * 128 + 64 + d] = m * iv * LOG2E;
        logdet += logf(v);
        quad   += m * m * iv;
    }
    const float LN2PI = 1.8378770664093453f;
    float c = -0.5f * (64.0f * LN2PI + logdet + quad) + logf(pi[k]);
    g_c[k] = c * LOG2E;
}

// ---------------- main fused kernel ------------------------------
extern __shared__ float smem[];

__global__ __launch_bounds__(NTHREADS, 2)
void fv_main_kernel(const float* __restrict__ x) {
    float* W_sh = smem + SM_W;
    float* f_sh = smem + SM_F;
    float* L_sh = smem + SM_L;
    float* c_sh = smem + SM_C;

    const int tid = threadIdx.x;

    // load weights once per CTA
    for (int i = tid; i < KK * 128; i += NTHREADS) W_sh[i] = g_W[i];
    if (tid < KK) c_sh[tid] = g_c[tid];

    const int b = blockIdx.x / SPLIT;
    const int s = blockIdx.x % SPLIT;
    const float* xb = x + ((size_t)b * NTOK + (size_t)s * TOK_PER_CTA) * DD;

    // phase-3 persistent accumulators: thread (ki, di)
    // owns k in {ki+16i}, d-pairs (2di,2di+1) and (2di+32,2di+33)
    const int ki = tid >> 4;
    const int di = tid & 15;
    unsigned long long aqx[4][2], aqx2[4][2];
    float qsum[4] = {0.f, 0.f, 0.f, 0.f};
#pragma unroll
    for (int i = 0; i < 4; i++) {
        aqx[i][0] = 0ull; aqx[i][1] = 0ull;
        aqx2[i][0] = 0ull; aqx2[i][1] = 0ull;
    }

    // phase-1 mapping: tokens tg+16tt, k = 4*kg+kk
    const int tg = tid & 15;
    const int kg = tid >> 4;

    for (int ch = 0; ch < NCHUNKS; ch++) {
        const float* xc = xb + (size_t)ch * TT * DD;
        __syncthreads();   // f_sh/L_sh reuse barrier (also covers W load on ch==0)

        // ---- phase 0: stage f = [x^2 | x] into shared ----
#pragma unroll
        for (int it = 0; it < 4; it++) {
            int f4 = tid + NTHREADS * it;       // 0..1023 float4 slots
            int t  = f4 >> 4;
            int c4 = f4 & 15;
            float4 v = ((const float4*)xc)[f4];
            float* frow = f_sh + t * FSTRIDE;
            int d0 = c4 * 4;
            frow[64 + d0]     = v.x; frow[64 + d0 + 1] = v.y;
            frow[64 + d0 + 2] = v.z; frow[64 + d0 + 3] = v.w;
            frow[d0]     = v.x * v.x; frow[d0 + 1] = v.y * v.y;
            frow[d0 + 2] = v.z * v.z; frow[d0 + 3] = v.w * v.w;
        }
        __syncthreads();

        // ---- phase 1: logits (4 tokens x 4 k per thread, f32x2 over j) ----
        {
            unsigned long long acc[4][4];
#pragma unroll
            for (int a = 0; a < 4; a++)
#pragma unroll
                for (int c = 0; c < 4; c++) acc[a][c] = 0ull;

            const float* wbase = W_sh + (kg * 4) * 128;
#pragma unroll 4
            for (int jp = 0; jp < 64; jp++) {
                unsigned long long fv[4], wv[4];
#pragma unroll
                for (int t4 = 0; t4 < 4; t4++)
                    fv[t4] = *(const unsigned long long*)(f_sh + (tg + 16 * t4) * FSTRIDE + 2 * jp);
#pragma unroll
                for (int k4 = 0; k4 < 4; k4++)
                    wv[k4] = *(const unsigned long long*)(wbase + k4 * 128 + 2 * jp);
#pragma unroll
                for (int t4 = 0; t4 < 4; t4++)
#pragma unroll
                    for (int k4 = 0; k4 < 4; k4++)
                        fma2(acc[t4][k4], fv[t4], wv[k4]);
            }
#pragma unroll
            for (int t4 = 0; t4 < 4; t4++) {
                int t = tg + 16 * t4;
#pragma unroll
                for (int k4 = 0; k4 < 4; k4++) {
                    int k = 4 * kg + k4;
                    float2 a = unpk(acc[t4][k4]);
                    L_sh[t * LSTRIDE + k] = a.x + a.y + c_sh[k];
                }
            }
        }
        __syncthreads();

        // ---- phase 2: softmax over K=64 per token (warp per 8 tokens) ----
        {
            const int wid = tid >> 5;
            const int lane = tid & 31;
#pragma unroll 2
            for (int t8 = 0; t8 < 8; t8++) {
                int t = wid * 8 + t8;
                float l0 = L_sh[t * LSTRIDE + lane];
                float l1 = L_sh[t * LSTRIDE + lane + 32];
                float m = fmaxf(l0, l1);
#pragma unroll
                for (int o = 16; o > 0; o >>= 1)
                    m = fmaxf(m, __shfl_xor_sync(0xffffffffu, m, o));
                float e0 = ex2f(l0 - m);
                float e1 = ex2f(l1 - m);
                float ssum = e0 + e1;
#pragma unroll
                for (int o = 16; o > 0; o >>= 1)
                    ssum += __shfl_xor_sync(0xffffffffu, ssum, o);
                float inv = __frcp_rn(ssum);
                L_sh[t * LSTRIDE + lane]      = e0 * inv;
                L_sh[t * LSTRIDE + lane + 32] = e1 * inv;
            }
        }
        __syncthreads();

        // ---- phase 3: accumulate Q_sum, Q^T x, Q^T x^2 (f32x2 outer products) ----
        {
#pragma unroll 2
            for (int t = 0; t < TT; t++) {
                const float* frow = f_sh + t * FSTRIDE;
                const float* lrow = L_sh + t * LSTRIDE;
                unsigned long long xp0 = *(const unsigned long long*)(frow + 64 + 2 * di);
                unsigned long long xp1 = *(const unsigned long long*)(frow + 64 + 32 + 2 * di);
                unsigned long long sp0 = *(const unsigned long long*)(frow + 2 * di);
                unsigned long long sp1 = *(const unsigned long long*)(frow + 32 + 2 * di);
#pragma unroll
                for (int i = 0; i < 4; i++) {
                    float q = lrow[ki + 16 * i];
                    unsigned long long q2 = pack2(q);
                    fma2(aqx[i][0], q2, xp0);
                    fma2(aqx[i][1], q2, xp1);
                    fma2(aqx2[i][0], q2, sp0);
                    fma2(aqx2[i][1], q2, sp1);
                    if (di == 0) qsum[i] += q;
                }
            }
        }
    }

    // ---- write per-CTA partials: [qsum 64][qx 64x64][qx2 64x64] ----
    float* outp = g_scratch + (size_t)blockIdx.x * PSIZE;
    if (di == 0) {
#pragma unroll
        for (int i = 0; i < 4; i++) outp[ki + 16 * i] = qsum[i];
    }
#pragma unroll
    for (int i = 0; i < 4; i++) {
        int k = ki + 16 * i;
#pragma unroll
        for (int p = 0; p < 2; p++) {
            int d0 = 2 * di + 32 * p;
            float2 v = unpk(aqx[i][p]);
            outp[64 + k * 64 + d0]     = v.x;
            outp[64 + k * 64 + d0 + 1] = v.y;
            float2 w = unpk(aqx2[i][p]);
            outp[64 + 4096 + k * 64 + d0]     = w.x;
            outp[64 + 4096 + k * 64 + d0 + 1] = w.y;
        }
    }
}

// ---------------- reduce + finalize ------------------------------
__global__ void fv_reduce_kernel(const float* __restrict__ pi,
                                 const float* __restrict__ mu,
                                 const float* __restrict__ var,
                                 float* __restrict__ out) {
    int idx = blockIdx.x * blockDim.x + threadIdx.x;   // 0 .. B*K*D-1
    if (idx >= BB * KK * DD) return;
    int b  = idx >> 12;        // /4096
    int kd = idx & 4095;
    int k  = kd >> 6;
    int d  = kd & 63;

    float qs = 0.f, qx = 0.f, qx2 = 0.f;
    const float* base = g_scratch + (size_t)(b * SPLIT) * PSIZE;
    for (int s2 = 0; s2 < SPLIT; s2++) {
        const float* p = base + (size_t)s2 * PSIZE;
        qs  += p[k];
        qx  += p[64 + kd];
        qx2 += p[64 + 4096 + kd];
    }
    const float invN = 1.0f / (float)NTOK;
    qs *= invN; qx *= invN; qx2 *= invN;

    float m = mu[kd];
    float v = var[kd];
    float* ob = out + (size_t)b * 8256;
    ob[64 + kd]        = qx - qs * m;
    ob[64 + 4096 + kd] = -qx2 - qs * m * m + qs * v + 2.0f * qx * m;
    if (d == 0) ob[k] = qs - pi[k];
}

// ---------------- launch -----------------------------------------
extern "C" void kernel_launch(void* const* d_in, const int* in_sizes, int n_in,
                              void* d_out, int out_size) {
    const float* x   = (const float*)d_in[0];
    const float* pi  = (const float*)d_in[1];
    const float* mu  = (const float*)d_in[2];
    const float* var = (const float*)d_in[3];
    float* out = (float*)d_out;

    cudaFuncSetAttribute(fv_main_kernel,
                         cudaFuncAttributeMaxDynamicSharedMemorySize, SMEM_BYTES);

    fv_prep_kernel<<<1, 64>>>(pi, mu, var);
    fv_main_kernel<<<BB * SPLIT, NTHREADS, SMEM_BYTES>>>(x);
    fv_reduce_kernel<<<(BB * KK * DD + 255) / 256, 256>>>(pi, mu, var, out);
}

// round 2
// speedup vs baseline: 1.1852x; 1.1852x over previous
#include <cuda_runtime.h>
#include <math.h>

// Problem constants
#define KK 64
#define DD 64
#define BB 16
#define NTOK 16384
#define TT 64                        // tokens per chunk
#define NCHUNK_TOTAL (BB * NTOK / TT)   // 4096 chunks over all batches
#define GRID 296                     // persistent: 148 SMs x occ 2, single wave
#define NTHREADS 256
#define PSIZE (KK + 2 * KK * DD)     // 8256 partial floats per slot

#define FSTRIDE 130                  // f_sh row stride (floats)
#define LSTRIDE 66                   // logits/Q row stride
#define LOG2E 1.4426950408889634f

// smem layout (floats): W[8192] | f[64*130=8320] | L[64*66=4224] | c[64]
#define SM_W 0
#define SM_F 8192
#define SM_L (8192 + 8320)
#define SM_C (SM_L + 4224)
#define SMEM_FLOATS (SM_C + 64)
#define SMEM_BYTES (SMEM_FLOATS * 4)   // 83200

__device__ float g_W[KK * 128];
__device__ float g_c[KK];
__device__ float g_scratch[GRID * 2 * PSIZE];   // 592 slots
__device__ int   g_tag[GRID * 2];

// ---------------- packed f32x2 helpers (sm_100+) ----------------
__device__ __forceinline__ void fma2(unsigned long long &d,
                                     unsigned long long a,
                                     unsigned long long b) {
    asm("fma.rn.f32x2 %0, %1, %2, %0;" : "+l"(d) : "l"(a), "l"(b));
}
__device__ __forceinline__ unsigned long long pack2(float x) {
    unsigned long long r;
    asm("mov.b64 %0, {%1, %1};" : "=l"(r) : "f"(x));
    return r;
}
__device__ __forceinline__ float2 unpk(unsigned long long v) {
    float2 r;
    asm("mov.b64 {%0, %1}, %2;" : "=f"(r.x), "=f"(r.y) : "l"(v));
    return r;
}
__device__ __forceinline__ float ex2f(float x) {
    float r;
    asm("ex2.approx.f32 %0, %1;" : "=f"(r) : "f"(x));
    return r;
}

// ---------------- prep: fold weights/constants (parallel) --------
// one CTA per k, 64 threads (one per d), warp+smem reduction
__global__ void fv_prep_kernel(const float* __restrict__ pi,
                               const float* __restrict__ mu,
                               const float* __restrict__ var) {
    __shared__ float red[2];
    const int k = blockIdx.x;
    const int d = threadIdx.x;
    float v = var[k * DD + d];
    float m = mu[k * DD + d];
    float iv = 1.0f / v;
    g_W[k * 128 + d]      = -0.5f * iv * LOG2E;
    g_W[k * 128 + 64 + d] = m * iv * LOG2E;
    float part = logf(v) + m * m * iv;      // logdet + quad combined
#pragma unroll
    for (int o = 16; o > 0; o >>= 1)
        part += __shfl_xor_sync(0xffffffffu, part, o);
    if ((d & 31) == 0) red[d >> 5] = part;
    __syncthreads();
    if (d == 0) {
        const float LN2PI = 1.8378770664093453f;
        float tot = red[0] + red[1];
        float c = -0.5f * (64.0f * LN2PI + tot) + logf(pi[k]);
        g_c[k] = c * LOG2E;
    }
}

// ---------------- main fused kernel (persistent) ------------------
extern __shared__ float smem[];

__global__ __launch_bounds__(NTHREADS, 2)
void fv_main_kernel(const float* __restrict__ x) {
    float* W_sh = smem + SM_W;
    float* f_sh = smem + SM_F;
    float* L_sh = smem + SM_L;
    float* c_sh = smem + SM_C;

    const int tid = threadIdx.x;
    const int bid = blockIdx.x;

    // load weights once per CTA
    for (int i = tid; i < KK * 128; i += NTHREADS) W_sh[i] = g_W[i];
    if (tid < KK) c_sh[tid] = g_c[tid];

    // chunk range for this CTA (balanced partition of 4096 over 296)
    const int s_lo = (bid * NCHUNK_TOTAL) / GRID;
    const int s_hi = ((bid + 1) * NCHUNK_TOTAL) / GRID;

    // phase-3 accumulators: thread (ki, di) owns k in {ki+16i},
    // d-pairs (2di,2di+1) and (2di+32,2di+33)
    const int ki = tid >> 4;
    const int di = tid & 15;
    unsigned long long aqx[4][2], aqx2[4][2];
    float qsum[4];
#pragma unroll
    for (int i = 0; i < 4; i++) {
        aqx[i][0] = 0ull; aqx[i][1] = 0ull;
        aqx2[i][0] = 0ull; aqx2[i][1] = 0ull;
        qsum[i] = 0.f;
    }
    int slot = 0;
    int cur_b = s_lo >> 8;   // 256 chunks per batch

    // phase-1 mapping: tokens tg+16*t4, k = 4*kg+k4
    const int tg = tid & 15;
    const int kg = tid >> 4;

    // prefetch first chunk into registers
    const float4* xg = (const float4*)x;
    float4 pf[4];
#pragma unroll
    for (int it = 0; it < 4; it++)
        pf[it] = xg[(size_t)s_lo * 1024 + tid + NTHREADS * it];

    for (int c = s_lo; c < s_hi; c++) {
        __syncthreads();   // f_sh/L_sh reuse barrier (covers W load on first iter)

        // ---- phase 0: stage f = [x^2 | x] into shared from registers ----
#pragma unroll
        for (int it = 0; it < 4; it++) {
            int f4 = tid + NTHREADS * it;       // 0..1023 float4 slots
            int t  = f4 >> 4;
            int c4 = f4 & 15;
            float4 v = pf[it];
            float* frow = f_sh + t * FSTRIDE;
            int d0 = c4 * 4;
            frow[64 + d0]     = v.x; frow[64 + d0 + 1] = v.y;
            frow[64 + d0 + 2] = v.z; frow[64 + d0 + 3] = v.w;
            frow[d0]     = v.x * v.x; frow[d0 + 1] = v.y * v.y;
            frow[d0 + 2] = v.z * v.z; frow[d0 + 3] = v.w * v.w;
        }
        __syncthreads();

        // prefetch next chunk (in flight during phases 1-3)
        if (c + 1 < s_hi) {
#pragma unroll
            for (int it = 0; it < 4; it++)
                pf[it] = xg[(size_t)(c + 1) * 1024 + tid + NTHREADS * it];
        }

        // ---- phase 1: logits (4 tokens x 4 k per thread, f32x2 over j) ----
        {
            unsigned long long acc[4][4];
#pragma unroll
            for (int a = 0; a < 4; a++)
#pragma unroll
                for (int cc = 0; cc < 4; cc++) acc[a][cc] = 0ull;

            const float* wbase = W_sh + (kg * 4) * 128;
#pragma unroll 4
            for (int jp = 0; jp < 64; jp++) {
                unsigned long long fv[4], wv[4];
#pragma unroll
                for (int t4 = 0; t4 < 4; t4++)
                    fv[t4] = *(const unsigned long long*)(f_sh + (tg + 16 * t4) * FSTRIDE + 2 * jp);
#pragma unroll
                for (int k4 = 0; k4 < 4; k4++)
                    wv[k4] = *(const unsigned long long*)(wbase + k4 * 128 + 2 * jp);
#pragma unroll
                for (int t4 = 0; t4 < 4; t4++)
#pragma unroll
                    for (int k4 = 0; k4 < 4; k4++)
                        fma2(acc[t4][k4], fv[t4], wv[k4]);
            }
#pragma unroll
            for (int t4 = 0; t4 < 4; t4++) {
                int t = tg + 16 * t4;
#pragma unroll
                for (int k4 = 0; k4 < 4; k4++) {
                    int k = 4 * kg + k4;
                    float2 a = unpk(acc[t4][k4]);
                    L_sh[t * LSTRIDE + k] = a.x + a.y + c_sh[k];
                }
            }
        }
        __syncthreads();

        // ---- phase 2: softmax over K=64 per token (warp per 8 tokens) ----
        {
            const int wid = tid >> 5;
            const int lane = tid & 31;
#pragma unroll
            for (int t8 = 0; t8 < 8; t8++) {
                int t = wid * 8 + t8;
                float l0 = L_sh[t * LSTRIDE + lane];
                float l1 = L_sh[t * LSTRIDE + lane + 32];
                float m = fmaxf(l0, l1);
#pragma unroll
                for (int o = 16; o > 0; o >>= 1)
                    m = fmaxf(m, __shfl_xor_sync(0xffffffffu, m, o));
                float e0 = ex2f(l0 - m);
                float e1 = ex2f(l1 - m);
                float ssum = e0 + e1;
#pragma unroll
                for (int o = 16; o > 0; o >>= 1)
                    ssum += __shfl_xor_sync(0xffffffffu, ssum, o);
                float inv = __frcp_rn(ssum);
                L_sh[t * LSTRIDE + lane]      = e0 * inv;
                L_sh[t * LSTRIDE + lane + 32] = e1 * inv;
            }
        }
        __syncthreads();

        // ---- phase 3: accumulate Q_sum, Q^T x, Q^T x^2 ----
        {
#pragma unroll 2
            for (int t = 0; t < TT; t++) {
                const float* frow = f_sh + t * FSTRIDE;
                const float* lrow = L_sh + t * LSTRIDE;
                unsigned long long xp0 = *(const unsigned long long*)(frow + 64 + 2 * di);
                unsigned long long xp1 = *(const unsigned long long*)(frow + 64 + 32 + 2 * di);
                unsigned long long sp0 = *(const unsigned long long*)(frow + 2 * di);
                unsigned long long sp1 = *(const unsigned long long*)(frow + 32 + 2 * di);
#pragma unroll
                for (int i = 0; i < 4; i++) {
                    float q = lrow[ki + 16 * i];
                    unsigned long long q2 = pack2(q);
                    fma2(aqx[i][0], q2, xp0);
                    fma2(aqx[i][1], q2, xp1);
                    fma2(aqx2[i][0], q2, sp0);
                    fma2(aqx2[i][1], q2, sp1);
                    if (di == 0) qsum[i] += q;
                }
            }
        }

        // ---- flush partials at batch boundary / end of range ----
        int nb = (c + 1) >> 8;
        if (c + 1 == s_hi || nb != cur_b) {
            float* outp = g_scratch + (size_t)(bid * 2 + slot) * PSIZE;
            if (tid == 0) g_tag[bid * 2 + slot] = cur_b;
            if (di == 0) {
#pragma unroll
                for (int i = 0; i < 4; i++) outp[ki + 16 * i] = qsum[i];
            }
#pragma unroll
            for (int i = 0; i < 4; i++) {
                int k = ki + 16 * i;
#pragma unroll
                for (int p = 0; p < 2; p++) {
                    int d0 = 2 * di + 32 * p;
                    float2 v = unpk(aqx[i][p]);
                    outp[64 + k * 64 + d0]     = v.x;
                    outp[64 + k * 64 + d0 + 1] = v.y;
                    float2 w = unpk(aqx2[i][p]);
                    outp[64 + 4096 + k * 64 + d0]     = w.x;
                    outp[64 + 4096 + k * 64 + d0 + 1] = w.y;
                }
            }
            // reset accumulators for next segment
#pragma unroll
            for (int i = 0; i < 4; i++) {
                aqx[i][0] = 0ull; aqx[i][1] = 0ull;
                aqx2[i][0] = 0ull; aqx2[i][1] = 0ull;
                qsum[i] = 0.f;
            }
            slot++;
            cur_b = nb;
        }
    }
    // mark unused slot(s)
    if (tid == 0) {
        for (int sl = slot; sl < 2; sl++) g_tag[bid * 2 + sl] = -1;
    }
}

// ---------------- reduce + finalize ------------------------------
__global__ void fv_reduce_kernel(const float* __restrict__ pi,
                                 const float* __restrict__ mu,
                                 const float* __restrict__ var,
                                 float* __restrict__ out) {
    int idx = blockIdx.x * blockDim.x + threadIdx.x;   // 0 .. B*K*D-1
    if (idx >= BB * KK * DD) return;
    int b  = idx >> 12;        // /4096
    int kd = idx & 4095;
    int k  = kd >> 6;
    int d  = kd & 63;

    // CTAs whose chunk range can overlap batch b (monotone partition)
    int i_lo = (GRID * b) / 16 - 1;       // floor(18.5*b) - 1
    if (i_lo < 0) i_lo = 0;
    int i_hi = (GRID * (b + 1)) / 16 + 1; // floor(18.5*(b+1)) + 1
    if (i_hi > GRID - 1) i_hi = GRID - 1;

    float qs = 0.f, qx = 0.f, qx2 = 0.f;
    for (int i = i_lo; i <= i_hi; i++) {
#pragma unroll
        for (int sl = 0; sl < 2; sl++) {
            int sid = 2 * i + sl;
            if (g_tag[sid] == b) {
                const float* p = g_scratch + (size_t)sid * PSIZE;
                qs  += p[k];
                qx  += p[64 + kd];
                qx2 += p[64 + 4096 + kd];
            }
        }
    }
    const float invN = 1.0f / (float)NTOK;
    qs *= invN; qx *= invN; qx2 *= invN;

    float m = mu[kd];
    float v = var[kd];
    float* ob = out + (size_t)b * 8256;
    ob[64 + kd]        = qx - qs * m;
    ob[64 + 4096 + kd] = -qx2 - qs * m * m + qs * v + 2.0f * qx * m;
    if (d == 0) ob[k] = qs - pi[k];
}

// ---------------- launch -----------------------------------------
extern "C" void kernel_launch(void* const* d_in, const int* in_sizes, int n_in,
                              void* d_out, int out_size) {
    const float* x   = (const float*)d_in[0];
    const float* pi  = (const float*)d_in[1];
    const float* mu  = (const float*)d_in[2];
    const float* var = (const float*)d_in[3];
    float* out = (float*)d_out;

    cudaFuncSetAttribute(fv_main_kernel,
                         cudaFuncAttributeMaxDynamicSharedMemorySize, SMEM_BYTES);

    fv_prep_kernel<<<KK, DD>>>(pi, mu, var);
    fv_main_kernel<<<GRID, NTHREADS, SMEM_BYTES>>>(x);
    fv_reduce_kernel<<<(BB * KK * DD + 255) / 256, 256>>>(pi, mu, var, out);
}